// round 4
// baseline (speedup 1.0000x reference)
#include <cuda_runtime.h>
#include <cuda_bf16.h>

// Problem constants
#define NN   10000
#define EE   30000
#define D_IN 64
#define E_DIM 16
#define H1   128
#define H2   64
#define CC   10
#define KX   17            // E_DIM + 1 bias slot
#define Q1W  (KX*H2)       // 1088
#define Q2W  (KX*CC)       // 170
#define B1W  (Q1W + H2)    // 1152 = q1 cols + root1 cols
#define B2W  (Q2W + CC)    // 180  = q2 cols + root2 cols

// ---------------- device scratch ----------------
__device__ float g_h1[NN*H1];
__device__ float g_q1[NN*Q1W];
__device__ float g_agg1[NN*H2];
__device__ float g_h2[NN*H2];
__device__ float g_q2[NN*Q2W];
__device__ float g_agg2[NN*CC];
__device__ float g_M1[H1*B1W];     // [i][col]: col<1088 -> We1/be1 packed, col>=1088 -> root1[i][col-1088]
__device__ float g_M2[H2*B2W];     // [j][col]: col<170  -> We2/be2 packed, col>=170  -> root2[j][col-170]

// ---------------- pack kernels ----------------
__global__ void pack_m1(const float* __restrict__ We1, const float* __restrict__ be1,
                        const float* __restrict__ root1) {
    int idx = blockIdx.x * blockDim.x + threadIdx.x;
    if (idx >= H1 * B1W) return;
    int i = idx / B1W;
    int col = idx - i * B1W;
    float v;
    if (col < Q1W) {
        int k = col / H2;
        int o = col - k * H2;
        v = (k < E_DIM) ? We1[k * (H1 * H2) + i * H2 + o] : be1[i * H2 + o];
    } else {
        v = root1[i * H2 + (col - Q1W)];
    }
    g_M1[idx] = v;
}

__global__ void pack_m2(const float* __restrict__ We2, const float* __restrict__ be2,
                        const float* __restrict__ root2) {
    int idx = blockIdx.x * blockDim.x + threadIdx.x;
    if (idx >= H2 * B2W) return;
    int j = idx / B2W;
    int col = idx - j * B2W;
    float v;
    if (col < Q2W) {
        int k = col / CC;
        int c = col - k * CC;
        v = (k < E_DIM) ? We2[k * (H2 * CC) + j * CC + c] : be2[j * CC + c];
    } else {
        v = root2[j * CC + (col - Q2W)];
    }
    g_M2[idx] = v;
}

// ========== double-buffered 128x128 SGEMM with split epilogue ==========
// C cols [0,S)   -> Cq (row stride S),   + biasQ, optional relu
// C cols [S,Nn)  -> Ca (row stride Nn-S), + biasA
// Requires K % 8 == 0, Nn % 4 == 0.
#define GM 128
#define GN 128
#define GK 8
__global__ __launch_bounds__(256, 2) void sgemm128x(
    const float* __restrict__ A, const float* __restrict__ B,
    float* __restrict__ Cq, float* __restrict__ Ca,
    int M, int Nn, int K, int S,
    const float* __restrict__ biasQ, const float* __restrict__ biasA, int do_relu)
{
    __shared__ float As[2][GK][GM];
    __shared__ float Bs[2][GK][GN];

    int tid = threadIdx.x;
    int tx = tid & 15;
    int ty = tid >> 4;
    int bm0 = blockIdx.y * GM;
    int bn0 = blockIdx.x * GN;

    // staging-load coordinates
    int arow = tid >> 1;             // 0..127
    int akq  = (tid & 1) * 4;        // 0 or 4
    int brow = tid >> 5;             // 0..7
    int bcol = (tid & 31) * 4;       // 0..124
    int agm  = bm0 + arow;
    int bgn  = bn0 + bcol;
    bool aok = (agm < M);
    bool bok = (bgn < Nn);
    const float* Abase = A + (size_t)agm * K + akq;

    float acc[8][8];
    #pragma unroll
    for (int i = 0; i < 8; i++)
        #pragma unroll
        for (int j = 0; j < 8; j++) acc[i][j] = 0.f;

    // prologue: tile 0 -> buffer 0
    {
        float4 av = make_float4(0.f,0.f,0.f,0.f), bv = make_float4(0.f,0.f,0.f,0.f);
        if (aok) av = *(const float4*)(Abase);
        if (bok) bv = *(const float4*)(B + (size_t)brow * Nn + bgn);
        As[0][akq + 0][arow] = av.x;
        As[0][akq + 1][arow] = av.y;
        As[0][akq + 2][arow] = av.z;
        As[0][akq + 3][arow] = av.w;
        *(float4*)&Bs[0][brow][bcol] = bv;
    }
    __syncthreads();

    int ntiles = K / GK;
    for (int kt = 0; kt < ntiles; kt++) {
        int cur = kt & 1;
        int nxt = cur ^ 1;
        float4 av, bv;
        bool more = (kt + 1 < ntiles);
        if (more) {
            int k0 = (kt + 1) * GK;
            av = make_float4(0.f,0.f,0.f,0.f);
            bv = make_float4(0.f,0.f,0.f,0.f);
            if (aok) av = *(const float4*)(Abase + k0);
            if (bok) bv = *(const float4*)(B + (size_t)(k0 + brow) * Nn + bgn);
        }

        #pragma unroll
        for (int k = 0; k < GK; k++) {
            float ra[8], rb[8];
            *(float4*)&ra[0] = *(const float4*)&As[cur][k][ty * 4];
            *(float4*)&ra[4] = *(const float4*)&As[cur][k][ty * 4 + 64];
            *(float4*)&rb[0] = *(const float4*)&Bs[cur][k][tx * 4];
            *(float4*)&rb[4] = *(const float4*)&Bs[cur][k][tx * 4 + 64];
            #pragma unroll
            for (int i = 0; i < 8; i++)
                #pragma unroll
                for (int j = 0; j < 8; j++)
                    acc[i][j] = fmaf(ra[i], rb[j], acc[i][j]);
        }

        if (more) {
            As[nxt][akq + 0][arow] = av.x;
            As[nxt][akq + 1][arow] = av.y;
            As[nxt][akq + 2][arow] = av.z;
            As[nxt][akq + 3][arow] = av.w;
            *(float4*)&Bs[nxt][brow][bcol] = bv;
            __syncthreads();
        }
    }

    // split epilogue (scalar; runs once)
    int Wa = Nn - S;
    #pragma unroll
    for (int ih = 0; ih < 2; ih++) {
        #pragma unroll
        for (int i = 0; i < 4; i++) {
            int gm = bm0 + ty * 4 + ih * 64 + i;
            if (gm >= M) continue;
            #pragma unroll
            for (int jh = 0; jh < 2; jh++) {
                #pragma unroll
                for (int j = 0; j < 4; j++) {
                    int gn = bn0 + tx * 4 + jh * 64 + j;
                    if (gn >= Nn) continue;
                    float v = acc[ih * 4 + i][jh * 4 + j];
                    if (gn < S) {
                        if (biasQ) v += biasQ[gn];
                        if (do_relu) v = fmaxf(v, 0.f);
                        Cq[(size_t)gm * S + gn] = v;
                    } else {
                        if (biasA) v += biasA[gn - S];
                        Ca[(size_t)gm * Wa + (gn - S)] = v;
                    }
                }
            }
        }
    }
}

// ---------------- edge kernels (warp per edge; edge_index is int32) ----------------
__global__ void edge_l1(const float* __restrict__ ea, const int* __restrict__ ei, int E) {
    int e = blockIdx.x * (blockDim.x >> 5) + (threadIdx.x >> 5);
    if (e >= E) return;
    int lane = threadIdx.x & 31;
    float cv = (lane < E_DIM) ? ea[(size_t)e * E_DIM + lane] : (lane == E_DIM ? 1.f : 0.f);
    int src = ei[e];
    int dst = ei[E + e];
    if ((unsigned)src >= NN || (unsigned)dst >= NN) return;
    const float* q = g_q1 + (size_t)src * Q1W;
    float a0 = 0.f, a1 = 0.f;
    #pragma unroll
    for (int k = 0; k < KX; k++) {
        float ck = __shfl_sync(0xffffffffu, cv, k);
        a0 = fmaf(ck, q[k * H2 + lane], a0);
        a1 = fmaf(ck, q[k * H2 + lane + 32], a1);
    }
    atomicAdd(&g_agg1[(size_t)dst * H2 + lane], a0);
    atomicAdd(&g_agg1[(size_t)dst * H2 + lane + 32], a1);
}

__global__ void edge_l2(const float* __restrict__ ea, const int* __restrict__ ei, int E) {
    int e = blockIdx.x * (blockDim.x >> 5) + (threadIdx.x >> 5);
    if (e >= E) return;
    int lane = threadIdx.x & 31;
    float cv = (lane < E_DIM) ? ea[(size_t)e * E_DIM + lane] : (lane == E_DIM ? 1.f : 0.f);
    int src = ei[e];
    int dst = ei[E + e];
    if ((unsigned)src >= NN || (unsigned)dst >= NN) return;
    const float* q = g_q2 + (size_t)src * Q2W;
    float a = 0.f;
    #pragma unroll
    for (int k = 0; k < KX; k++) {
        float ck = __shfl_sync(0xffffffffu, cv, k);
        if (lane < CC) a = fmaf(ck, q[k * CC + lane], a);
    }
    if (lane < CC) atomicAdd(&g_agg2[(size_t)dst * CC + lane], a);
}

// ---------------- relu + log_softmax ----------------
__global__ void relu_copy(int n) {
    int i = blockIdx.x * blockDim.x + threadIdx.x;
    if (i < n) g_h2[i] = fmaxf(g_agg1[i], 0.f);
}

__global__ void log_softmax_rows(float* __restrict__ out, int n) {
    int r = blockIdx.x * blockDim.x + threadIdx.x;
    if (r >= n) return;
    const float* z = g_agg2 + (size_t)r * CC;
    float m = z[0];
    #pragma unroll
    for (int c = 1; c < CC; c++) m = fmaxf(m, z[c]);
    float s = 0.f;
    #pragma unroll
    for (int c = 0; c < CC; c++) s += __expf(z[c] - m);
    float ls = m + logf(s);
    #pragma unroll
    for (int c = 0; c < CC; c++) out[(size_t)r * CC + c] = z[c] - ls;
}

// ---------------- launch ----------------
extern "C" void kernel_launch(void* const* d_in, const int* in_sizes, int n_in,
                              void* d_out, int out_size)
{
    const float* x     = (const float*)d_in[0];
    const float* ea    = (const float*)d_in[1];
    const int*   ei    = (const int*)d_in[2];
    const float* W1    = (const float*)d_in[3];
    const float* b1    = (const float*)d_in[4];
    const float* We1   = (const float*)d_in[5];
    const float* be1   = (const float*)d_in[6];
    const float* root1 = (const float*)d_in[7];
    const float* bias1 = (const float*)d_in[8];
    const float* We2   = (const float*)d_in[9];
    const float* be2   = (const float*)d_in[10];
    const float* root2 = (const float*)d_in[11];
    const float* bias2 = (const float*)d_in[12];
    float* out = (float*)d_out;

    int N = in_sizes[0] / D_IN;
    int E = in_sizes[2] / 2;

    float *p_h1, *p_q1, *p_agg1, *p_h2, *p_q2, *p_M1, *p_M2, *p_agg2;
    cudaGetSymbolAddress((void**)&p_h1,   g_h1);
    cudaGetSymbolAddress((void**)&p_q1,   g_q1);
    cudaGetSymbolAddress((void**)&p_agg1, g_agg1);
    cudaGetSymbolAddress((void**)&p_h2,   g_h2);
    cudaGetSymbolAddress((void**)&p_q2,   g_q2);
    cudaGetSymbolAddress((void**)&p_M1,   g_M1);
    cudaGetSymbolAddress((void**)&p_M2,   g_M2);
    cudaGetSymbolAddress((void**)&p_agg2, g_agg2);

    dim3 blk(256);

    pack_m1<<<(H1 * B1W + 255) / 256, blk>>>(We1, be1, root1);
    pack_m2<<<(H2 * B2W + 255) / 256, blk>>>(We2, be2, root2);

    // h1 = relu(x @ W1 + b1)            [N,64]@[64,128]
    {
        dim3 g((H1 + GN - 1) / GN, (N + GM - 1) / GM);
        sgemm128x<<<g, blk>>>(x, W1, p_h1, p_h1, N, H1, D_IN, H1, b1, nullptr, 1);
    }
    // fused q1|agg1 = h1 @ [M1|root1]   [N,128]@[128,1152]; split at 1088
    {
        dim3 g((B1W + GN - 1) / GN, (N + GM - 1) / GM);
        sgemm128x<<<g, blk>>>(p_h1, p_M1, p_q1, p_agg1, N, B1W, H1, Q1W, nullptr, bias1, 0);
    }
    edge_l1<<<(E + 3) / 4, 128>>>(ea, ei, E);
    relu_copy<<<(N * H2 + 255) / 256, blk>>>(N * H2);
    // fused q2|agg2 = h2 @ [M2|root2]   [N,64]@[64,180]; split at 170
    {
        dim3 g((B2W + GN - 1) / GN, (N + GM - 1) / GM);
        sgemm128x<<<g, blk>>>(p_h2, p_M2, p_q2, p_agg2, N, B2W, H2, Q2W, nullptr, bias2, 0);
    }
    edge_l2<<<(E + 3) / 4, 128>>>(ea, ei, E);
    log_softmax_rows<<<(N + 255) / 256, blk>>>(out, N);
}

// round 5
// speedup vs baseline: 1.1702x; 1.1702x over previous
#include <cuda_runtime.h>
#include <cuda_bf16.h>

// Problem constants
#define NN   10000
#define EE   30000
#define D_IN 64
#define E_DIM 16
#define H1   128
#define H2   64
#define CC   10
#define KX   17            // E_DIM + 1 bias slot
#define Q1W  (KX*H2)       // 1088
#define Q2W  (KX*CC)       // 170
#define B1W  (Q1W + H2)    // 1152 = q1 cols + root1 cols
#define B2W  (Q2W + CC)    // 180  = q2 cols + root2 cols

// ---------------- device scratch ----------------
__device__ float g_h1[NN*H1];
__device__ float g_q1[NN*Q1W];
__device__ float g_agg1[NN*H2];
__device__ float g_h2[NN*H2];
__device__ float g_q2[NN*Q2W];
__device__ float g_agg2[NN*CC];
__device__ float g_M1[H1*B1W];
__device__ float g_M2[H2*B2W];

// ---------------- f32x2 packed helpers ----------------
__device__ __forceinline__ void ffma2(unsigned long long& d,
                                      unsigned long long a,
                                      unsigned long long b) {
    asm("fma.rn.f32x2 %0, %1, %2, %0;" : "+l"(d) : "l"(a), "l"(b));
}
__device__ __forceinline__ unsigned long long dup_f32(float v) {
    unsigned long long r;
    asm("mov.b64 %0, {%1, %1};" : "=l"(r) : "f"(v));
    return r;
}
__device__ __forceinline__ float2 unpack_f32x2(unsigned long long p) {
    float2 f;
    asm("mov.b64 {%0, %1}, %2;" : "=f"(f.x), "=f"(f.y) : "l"(p));
    return f;
}

// ---------------- pack kernels ----------------
__global__ void pack_m1(const float* __restrict__ We1, const float* __restrict__ be1,
                        const float* __restrict__ root1) {
    int idx = blockIdx.x * blockDim.x + threadIdx.x;
    if (idx >= H1 * B1W) return;
    int i = idx / B1W;
    int col = idx - i * B1W;
    float v;
    if (col < Q1W) {
        int k = col / H2;
        int o = col - k * H2;
        v = (k < E_DIM) ? We1[k * (H1 * H2) + i * H2 + o] : be1[i * H2 + o];
    } else {
        v = root1[i * H2 + (col - Q1W)];
    }
    g_M1[idx] = v;
}

__global__ void pack_m2(const float* __restrict__ We2, const float* __restrict__ be2,
                        const float* __restrict__ root2) {
    int idx = blockIdx.x * blockDim.x + threadIdx.x;
    if (idx >= H2 * B2W) return;
    int j = idx / B2W;
    int col = idx - j * B2W;
    float v;
    if (col < Q2W) {
        int k = col / CC;
        int c = col - k * CC;
        v = (k < E_DIM) ? We2[k * (H2 * CC) + j * CC + c] : be2[j * CC + c];
    } else {
        v = root2[j * CC + (col - Q2W)];
    }
    g_M2[idx] = v;
}

// ========== single-buffered 128x128 SGEMM, f32x2 packed FMA, split epilogue ==========
// C cols [0,S)  -> Cq (row stride S),    +biasQ, optional relu
// C cols [S,Nn) -> Ca (row stride Nn-S), +biasA
// Requires K % 8 == 0, Nn % 4 == 0.
#define GM 128
#define GN 128
#define GK 8
__global__ __launch_bounds__(256) void sgemm128x(
    const float* __restrict__ A, const float* __restrict__ B,
    float* __restrict__ Cq, float* __restrict__ Ca,
    int M, int Nn, int K, int S,
    const float* __restrict__ biasQ, const float* __restrict__ biasA, int do_relu)
{
    __shared__ float As[GK][GM];   // [k][m]
    __shared__ float Bs[GK][GN];   // [k][n]

    int tid = threadIdx.x;
    int tx = tid & 15;
    int ty = tid >> 4;
    int bm0 = blockIdx.y * GM;
    int bn0 = blockIdx.x * GN;

    int arow = tid >> 1;
    int akq  = (tid & 1) * 4;
    int brow = tid >> 5;
    int bcol = (tid & 31) * 4;
    int agm  = bm0 + arow;
    int bgn  = bn0 + bcol;
    bool aok = (agm < M);
    bool bok = (bgn < Nn);
    const float* Abase = A + (size_t)agm * K + akq;

    // packed accumulators: accp[i][jp] = cols (base+2jp, base+2jp+1); jp<2 -> jh=0, jp>=2 -> jh=1
    unsigned long long accp[8][4];
    #pragma unroll
    for (int i = 0; i < 8; i++)
        #pragma unroll
        for (int j = 0; j < 4; j++) accp[i][j] = 0ull;

    for (int k0 = 0; k0 < K; k0 += GK) {
        {
            float4 v = make_float4(0.f, 0.f, 0.f, 0.f);
            if (aok) v = *(const float4*)(Abase + k0);
            As[akq + 0][arow] = v.x;
            As[akq + 1][arow] = v.y;
            As[akq + 2][arow] = v.z;
            As[akq + 3][arow] = v.w;
        }
        {
            float4 v = make_float4(0.f, 0.f, 0.f, 0.f);
            if (bok) v = *(const float4*)(B + (size_t)(k0 + brow) * Nn + bgn);
            *(float4*)&Bs[brow][bcol] = v;
        }
        __syncthreads();

        #pragma unroll
        for (int k = 0; k < GK; k++) {
            float4 a0 = *(const float4*)&As[k][ty * 4];
            float4 a1 = *(const float4*)&As[k][ty * 4 + 64];
            // B fragments read directly as packed f32x2 pairs
            ulonglong2 b0 = *(const ulonglong2*)&Bs[k][tx * 4];        // cols tx*4..tx*4+3
            ulonglong2 b1 = *(const ulonglong2*)&Bs[k][tx * 4 + 64];   // cols +64
            unsigned long long ad[8];
            ad[0] = dup_f32(a0.x); ad[1] = dup_f32(a0.y);
            ad[2] = dup_f32(a0.z); ad[3] = dup_f32(a0.w);
            ad[4] = dup_f32(a1.x); ad[5] = dup_f32(a1.y);
            ad[6] = dup_f32(a1.z); ad[7] = dup_f32(a1.w);
            #pragma unroll
            for (int i = 0; i < 8; i++) {
                ffma2(accp[i][0], ad[i], b0.x);
                ffma2(accp[i][1], ad[i], b0.y);
                ffma2(accp[i][2], ad[i], b1.x);
                ffma2(accp[i][3], ad[i], b1.y);
            }
        }
        __syncthreads();
    }

    // scalar split epilogue (S may not be float4-aligned relative to tile)
    int Wa = Nn - S;
    #pragma unroll
    for (int ih = 0; ih < 2; ih++) {
        #pragma unroll
        for (int i = 0; i < 4; i++) {
            int gm = bm0 + ty * 4 + ih * 64 + i;
            if (gm >= M) continue;
            int ridx = ih * 4 + i;
            #pragma unroll
            for (int jh = 0; jh < 2; jh++) {
                #pragma unroll
                for (int jp = 0; jp < 2; jp++) {
                    float2 f = unpack_f32x2(accp[ridx][jh * 2 + jp]);
                    #pragma unroll
                    for (int l = 0; l < 2; l++) {
                        int gn = bn0 + tx * 4 + jh * 64 + jp * 2 + l;
                        if (gn >= Nn) continue;
                        float v = (l == 0) ? f.x : f.y;
                        if (gn < S) {
                            if (biasQ) v += biasQ[gn];
                            if (do_relu) v = fmaxf(v, 0.f);
                            Cq[(size_t)gm * S + gn] = v;
                        } else {
                            if (biasA) v += biasA[gn - S];
                            Ca[(size_t)gm * Wa + (gn - S)] = v;
                        }
                    }
                }
            }
        }
    }
}

// ---------------- edge kernels (warp per edge; edge_index is int32) ----------------
__global__ void edge_l1(const float* __restrict__ ea, const int* __restrict__ ei, int E) {
    int e = blockIdx.x * (blockDim.x >> 5) + (threadIdx.x >> 5);
    if (e >= E) return;
    int lane = threadIdx.x & 31;
    float cv = (lane < E_DIM) ? ea[(size_t)e * E_DIM + lane] : (lane == E_DIM ? 1.f : 0.f);
    int src = ei[e];
    int dst = ei[E + e];
    if ((unsigned)src >= NN || (unsigned)dst >= NN) return;
    const float* q = g_q1 + (size_t)src * Q1W;
    float a0 = 0.f, a1 = 0.f;
    #pragma unroll
    for (int k = 0; k < KX; k++) {
        float ck = __shfl_sync(0xffffffffu, cv, k);
        a0 = fmaf(ck, q[k * H2 + lane], a0);
        a1 = fmaf(ck, q[k * H2 + lane + 32], a1);
    }
    atomicAdd(&g_agg1[(size_t)dst * H2 + lane], a0);
    atomicAdd(&g_agg1[(size_t)dst * H2 + lane + 32], a1);
}

__global__ void edge_l2(const float* __restrict__ ea, const int* __restrict__ ei, int E) {
    int e = blockIdx.x * (blockDim.x >> 5) + (threadIdx.x >> 5);
    if (e >= E) return;
    int lane = threadIdx.x & 31;
    float cv = (lane < E_DIM) ? ea[(size_t)e * E_DIM + lane] : (lane == E_DIM ? 1.f : 0.f);
    int src = ei[e];
    int dst = ei[E + e];
    if ((unsigned)src >= NN || (unsigned)dst >= NN) return;
    const float* q = g_q2 + (size_t)src * Q2W;
    float a = 0.f;
    #pragma unroll
    for (int k = 0; k < KX; k++) {
        float ck = __shfl_sync(0xffffffffu, cv, k);
        if (lane < CC) a = fmaf(ck, q[k * CC + lane], a);
    }
    if (lane < CC) atomicAdd(&g_agg2[(size_t)dst * CC + lane], a);
}

// ---------------- relu + log_softmax ----------------
__global__ void relu_copy(int n) {
    int i = blockIdx.x * blockDim.x + threadIdx.x;
    if (i < n) g_h2[i] = fmaxf(g_agg1[i], 0.f);
}

__global__ void log_softmax_rows(float* __restrict__ out, int n) {
    int r = blockIdx.x * blockDim.x + threadIdx.x;
    if (r >= n) return;
    const float* z = g_agg2 + (size_t)r * CC;
    float m = z[0];
    #pragma unroll
    for (int c = 1; c < CC; c++) m = fmaxf(m, z[c]);
    float s = 0.f;
    #pragma unroll
    for (int c = 0; c < CC; c++) s += __expf(z[c] - m);
    float ls = m + logf(s);
    #pragma unroll
    for (int c = 0; c < CC; c++) out[(size_t)r * CC + c] = z[c] - ls;
}

// ---------------- launch ----------------
extern "C" void kernel_launch(void* const* d_in, const int* in_sizes, int n_in,
                              void* d_out, int out_size)
{
    const float* x     = (const float*)d_in[0];
    const float* ea    = (const float*)d_in[1];
    const int*   ei    = (const int*)d_in[2];
    const float* W1    = (const float*)d_in[3];
    const float* b1    = (const float*)d_in[4];
    const float* We1   = (const float*)d_in[5];
    const float* be1   = (const float*)d_in[6];
    const float* root1 = (const float*)d_in[7];
    const float* bias1 = (const float*)d_in[8];
    const float* We2   = (const float*)d_in[9];
    const float* be2   = (const float*)d_in[10];
    const float* root2 = (const float*)d_in[11];
    const float* bias2 = (const float*)d_in[12];
    float* out = (float*)d_out;

    int N = in_sizes[0] / D_IN;
    int E = in_sizes[2] / 2;

    float *p_h1, *p_q1, *p_agg1, *p_h2, *p_q2, *p_M1, *p_M2, *p_agg2;
    cudaGetSymbolAddress((void**)&p_h1,   g_h1);
    cudaGetSymbolAddress((void**)&p_q1,   g_q1);
    cudaGetSymbolAddress((void**)&p_agg1, g_agg1);
    cudaGetSymbolAddress((void**)&p_h2,   g_h2);
    cudaGetSymbolAddress((void**)&p_q2,   g_q2);
    cudaGetSymbolAddress((void**)&p_M1,   g_M1);
    cudaGetSymbolAddress((void**)&p_M2,   g_M2);
    cudaGetSymbolAddress((void**)&p_agg2, g_agg2);

    dim3 blk(256);

    pack_m1<<<(H1 * B1W + 255) / 256, blk>>>(We1, be1, root1);
    pack_m2<<<(H2 * B2W + 255) / 256, blk>>>(We2, be2, root2);

    // h1 = relu(x @ W1 + b1)            [N,64]@[64,128]
    {
        dim3 g((H1 + GN - 1) / GN, (N + GM - 1) / GM);
        sgemm128x<<<g, blk>>>(x, W1, p_h1, p_h1, N, H1, D_IN, H1, b1, nullptr, 1);
    }
    // fused q1|agg1 = h1 @ [M1|root1]   [N,128]@[128,1152]; split at 1088
    {
        dim3 g((B1W + GN - 1) / GN, (N + GM - 1) / GM);
        sgemm128x<<<g, blk>>>(p_h1, p_M1, p_q1, p_agg1, N, B1W, H1, Q1W, nullptr, bias1, 0);
    }
    edge_l1<<<(E + 3) / 4, 128>>>(ea, ei, E);
    relu_copy<<<(N * H2 + 255) / 256, blk>>>(N * H2);
    // fused q2|agg2 = h2 @ [M2|root2]   [N,64]@[64,180]; split at 170
    {
        dim3 g((B2W + GN - 1) / GN, (N + GM - 1) / GM);
        sgemm128x<<<g, blk>>>(p_h2, p_M2, p_q2, p_agg2, N, B2W, H2, Q2W, nullptr, bias2, 0);
    }
    edge_l2<<<(E + 3) / 4, 128>>>(ea, ei, E);
    log_softmax_rows<<<(N + 255) / 256, blk>>>(out, N);
}

// round 8
// speedup vs baseline: 1.5603x; 1.3333x over previous
#include <cuda_runtime.h>
#include <cuda_bf16.h>
#include <cstdint>

// Problem constants
#define NN   10000
#define EE   30000
#define D_IN 64
#define E_DIM 16
#define H1   128
#define H2   64
#define CC   10
#define KX   17            // E_DIM + 1 bias slot
#define Q1W  (KX*H2)       // 1088
#define Q2W  (KX*CC)       // 170
#define B1W  (Q1W + H2)    // 1152
#define B2W  (Q2W + CC)    // 180

// ---------------- device scratch ----------------
__device__ float g_h1[NN*H1];
__device__ float g_q1[NN*Q1W];
__device__ float g_agg1[NN*H2];
__device__ float g_h2[NN*H2];
__device__ float g_q2[NN*Q2W];
__device__ float g_agg2[NN*CC];
__device__ float g_M1[H1*B1W];
__device__ float g_M2[H2*B2W];

// ---------------- helpers ----------------
__device__ __forceinline__ uint32_t f2tf32(float f) {
    uint32_t r;
    asm("cvt.rna.tf32.f32 %0, %1;" : "=r"(r) : "f"(f));
    return r;
}

__device__ __forceinline__ void mma_tf32(float c[4], uint32_t a0, uint32_t a1,
                                         uint32_t a2, uint32_t a3,
                                         uint32_t b0, uint32_t b1) {
    asm volatile(
        "mma.sync.aligned.m16n8k8.row.col.f32.tf32.tf32.f32 "
        "{%0,%1,%2,%3}, {%4,%5,%6,%7}, {%8,%9}, {%0,%1,%2,%3};"
        : "+f"(c[0]), "+f"(c[1]), "+f"(c[2]), "+f"(c[3])
        : "r"(a0), "r"(a1), "r"(a2), "r"(a3), "r"(b0), "r"(b1));
}

// ---------------- pack kernels ----------------
__global__ void pack_m1(const float* __restrict__ We1, const float* __restrict__ be1,
                        const float* __restrict__ root1) {
    int idx = blockIdx.x * blockDim.x + threadIdx.x;
    if (idx >= H1 * B1W) return;
    int i = idx / B1W;
    int col = idx - i * B1W;
    float v;
    if (col < Q1W) {
        int k = col / H2;
        int o = col - k * H2;
        v = (k < E_DIM) ? We1[k * (H1 * H2) + i * H2 + o] : be1[i * H2 + o];
    } else {
        v = root1[i * H2 + (col - Q1W)];
    }
    g_M1[idx] = v;
}

__global__ void pack_m2(const float* __restrict__ We2, const float* __restrict__ be2,
                        const float* __restrict__ root2) {
    int idx = blockIdx.x * blockDim.x + threadIdx.x;
    if (idx >= H2 * B2W) return;
    int j = idx / B2W;
    int col = idx - j * B2W;
    float v;
    if (col < Q2W) {
        int k = col / CC;
        int c = col - k * CC;
        v = (k < E_DIM) ? We2[k * (H2 * CC) + j * CC + c] : be2[j * CC + c];
    } else {
        v = root2[j * CC + (col - Q2W)];
    }
    g_M2[idx] = v;
}

// ========== tf32 tensor-core GEMM: 128x128 tile, GK=16, 8 warps (2x4), split epilogue ==========
// C cols [0,S)  -> Cq (stride S) +biasQ (+relu);  cols [S,Nn) -> Ca (stride Nn-S) +biasA
// Requires K % 16 == 0, Nn % 4 == 0.
#define GM 128
#define GN 128
#define GKT 16
#define AKP 20     // As row pad: [128][20], conflict-free frag loads
#define BNP 136    // Bs row pad: [16][136]
__global__ __launch_bounds__(256) void tgemm(
    const float* __restrict__ A, const float* __restrict__ B,
    float* __restrict__ Cq, float* __restrict__ Ca,
    int M, int Nn, int K, int S,
    const float* __restrict__ biasQ, const float* __restrict__ biasA, int do_relu)
{
    __shared__ uint32_t As[GM][AKP];   // [m][k] tf32 bits
    __shared__ uint32_t Bs[GKT][BNP];  // [k][n] tf32 bits

    int tid  = threadIdx.x;
    int lane = tid & 31;
    int wid  = tid >> 5;
    int bm0 = blockIdx.y * GM;
    int bn0 = blockIdx.x * GN;
    int wm = (wid & 1) * 64;     // warp row offset
    int wn = (wid >> 1) * 32;    // warp col offset

    // staging coords
    int arow = tid >> 1;          // 0..127
    int ak   = (tid & 1) * 8;     // 0 or 8
    int brow = tid >> 4;          // 0..15
    int bcol = (tid & 15) * 8;    // 0..120
    bool aok  = (bm0 + arow) < M;
    const float* Abase = A + (size_t)(bm0 + arow) * K + ak;

    float c[4][4][4];
    #pragma unroll
    for (int mt = 0; mt < 4; mt++)
        #pragma unroll
        for (int nt = 0; nt < 4; nt++)
            #pragma unroll
            for (int r = 0; r < 4; r++) c[mt][nt][r] = 0.f;

    int lq = lane & 3;   // k-within-8 / col group
    int lg = lane >> 2;  // 0..7

    for (int k0 = 0; k0 < K; k0 += GKT) {
        // stage A: 128 x 16, two float4 per thread, cvt to tf32
        {
            float4 v0 = make_float4(0.f,0.f,0.f,0.f), v1 = v0;
            if (aok) {
                v0 = *(const float4*)(Abase + k0);
                v1 = *(const float4*)(Abase + k0 + 4);
            }
            As[arow][ak + 0] = f2tf32(v0.x);
            As[arow][ak + 1] = f2tf32(v0.y);
            As[arow][ak + 2] = f2tf32(v0.z);
            As[arow][ak + 3] = f2tf32(v0.w);
            As[arow][ak + 4] = f2tf32(v1.x);
            As[arow][ak + 5] = f2tf32(v1.y);
            As[arow][ak + 6] = f2tf32(v1.z);
            As[arow][ak + 7] = f2tf32(v1.w);
        }
        // stage B: 16 x 128, two guarded float4 per thread
        {
            const float* Brow = B + (size_t)(k0 + brow) * Nn + bn0 + bcol;
            float4 w0 = make_float4(0.f,0.f,0.f,0.f), w1 = w0;
            if (bn0 + bcol < Nn)     w0 = *(const float4*)(Brow);
            if (bn0 + bcol + 4 < Nn) w1 = *(const float4*)(Brow + 4);
            Bs[brow][bcol + 0] = f2tf32(w0.x);
            Bs[brow][bcol + 1] = f2tf32(w0.y);
            Bs[brow][bcol + 2] = f2tf32(w0.z);
            Bs[brow][bcol + 3] = f2tf32(w0.w);
            Bs[brow][bcol + 4] = f2tf32(w1.x);
            Bs[brow][bcol + 5] = f2tf32(w1.y);
            Bs[brow][bcol + 6] = f2tf32(w1.z);
            Bs[brow][bcol + 7] = f2tf32(w1.w);
        }
        __syncthreads();

        #pragma unroll
        for (int kk = 0; kk < GKT; kk += 8) {
            uint32_t af[4][4];
            #pragma unroll
            for (int mt = 0; mt < 4; mt++) {
                int m = wm + mt * 16 + lg;
                af[mt][0] = As[m    ][kk + lq];
                af[mt][1] = As[m + 8][kk + lq];
                af[mt][2] = As[m    ][kk + lq + 4];
                af[mt][3] = As[m + 8][kk + lq + 4];
            }
            uint32_t bf[4][2];
            #pragma unroll
            for (int nt = 0; nt < 4; nt++) {
                int n = wn + nt * 8 + lg;
                bf[nt][0] = Bs[kk + lq    ][n];
                bf[nt][1] = Bs[kk + lq + 4][n];
            }
            #pragma unroll
            for (int mt = 0; mt < 4; mt++)
                #pragma unroll
                for (int nt = 0; nt < 4; nt++)
                    mma_tf32(c[mt][nt], af[mt][0], af[mt][1], af[mt][2], af[mt][3],
                             bf[nt][0], bf[nt][1]);
        }
        __syncthreads();
    }

    // epilogue: c reg r -> row = base + (r>=2 ? 8 : 0) + lg, col = base + 2*lq + (r&1)
    int Wa = Nn - S;
    #pragma unroll
    for (int mt = 0; mt < 4; mt++) {
        #pragma unroll
        for (int rh = 0; rh < 2; rh++) {
            int gm = bm0 + wm + mt * 16 + rh * 8 + lg;
            if (gm >= M) continue;
            #pragma unroll
            for (int nt = 0; nt < 4; nt++) {
                #pragma unroll
                for (int l = 0; l < 2; l++) {
                    int gn = bn0 + wn + nt * 8 + 2 * lq + l;
                    if (gn >= Nn) continue;
                    float v = c[mt][nt][rh * 2 + l];
                    if (gn < S) {
                        if (biasQ) v += biasQ[gn];
                        if (do_relu) v = fmaxf(v, 0.f);
                        Cq[(size_t)gm * S + gn] = v;
                    } else {
                        if (biasA) v += biasA[gn - S];
                        Ca[(size_t)gm * Wa + (gn - S)] = v;
                    }
                }
            }
        }
    }
}

// ---------------- edge kernels (warp per edge; edge_index is int32) ----------------
__global__ void edge_l1(const float* __restrict__ ea, const int* __restrict__ ei, int E) {
    int e = blockIdx.x * (blockDim.x >> 5) + (threadIdx.x >> 5);
    if (e >= E) return;
    int lane = threadIdx.x & 31;
    float cv = (lane < E_DIM) ? ea[(size_t)e * E_DIM + lane] : (lane == E_DIM ? 1.f : 0.f);
    int src = ei[e];
    int dst = ei[E + e];
    if ((unsigned)src >= NN || (unsigned)dst >= NN) return;
    const float* q = g_q1 + (size_t)src * Q1W;
    float a0 = 0.f, a1 = 0.f;
    #pragma unroll
    for (int k = 0; k < KX; k++) {
        float ck = __shfl_sync(0xffffffffu, cv, k);
        a0 = fmaf(ck, q[k * H2 + lane], a0);
        a1 = fmaf(ck, q[k * H2 + lane + 32], a1);
    }
    atomicAdd(&g_agg1[(size_t)dst * H2 + lane], a0);
    atomicAdd(&g_agg1[(size_t)dst * H2 + lane + 32], a1);
}

__global__ void edge_l2(const float* __restrict__ ea, const int* __restrict__ ei, int E) {
    int e = blockIdx.x * (blockDim.x >> 5) + (threadIdx.x >> 5);
    if (e >= E) return;
    int lane = threadIdx.x & 31;
    float cv = (lane < E_DIM) ? ea[(size_t)e * E_DIM + lane] : (lane == E_DIM ? 1.f : 0.f);
    int src = ei[e];
    int dst = ei[E + e];
    if ((unsigned)src >= NN || (unsigned)dst >= NN) return;
    const float* q = g_q2 + (size_t)src * Q2W;
    float a = 0.f;
    #pragma unroll
    for (int k = 0; k < KX; k++) {
        float ck = __shfl_sync(0xffffffffu, cv, k);
        if (lane < CC) a = fmaf(ck, q[k * CC + lane], a);
    }
    if (lane < CC) atomicAdd(&g_agg2[(size_t)dst * CC + lane], a);
}

// ---------------- relu + log_softmax ----------------
__global__ void relu_copy(int n) {
    int i = blockIdx.x * blockDim.x + threadIdx.x;
    if (i < n) g_h2[i] = fmaxf(g_agg1[i], 0.f);
}

__global__ void log_softmax_rows(float* __restrict__ out, int n) {
    int r = blockIdx.x * blockDim.x + threadIdx.x;
    if (r >= n) return;
    const float* z = g_agg2 + (size_t)r * CC;
    float m = z[0];
    #pragma unroll
    for (int c = 1; c < CC; c++) m = fmaxf(m, z[c]);
    float s = 0.f;
    #pragma unroll
    for (int c = 0; c < CC; c++) s += __expf(z[c] - m);
    float ls = m + logf(s);
    #pragma unroll
    for (int c = 0; c < CC; c++) out[(size_t)r * CC + c] = z[c] - ls;
}

// ---------------- launch ----------------
extern "C" void kernel_launch(void* const* d_in, const int* in_sizes, int n_in,
                              void* d_out, int out_size)
{
    const float* x     = (const float*)d_in[0];
    const float* ea    = (const float*)d_in[1];
    const int*   ei    = (const int*)d_in[2];
    const float* W1    = (const float*)d_in[3];
    const float* b1    = (const float*)d_in[4];
    const float* We1   = (const float*)d_in[5];
    const float* be1   = (const float*)d_in[6];
    const float* root1 = (const float*)d_in[7];
    const float* bias1 = (const float*)d_in[8];
    const float* We2   = (const float*)d_in[9];
    const float* be2   = (const float*)d_in[10];
    const float* root2 = (const float*)d_in[11];
    const float* bias2 = (const float*)d_in[12];
    float* out = (float*)d_out;

    int N = in_sizes[0] / D_IN;
    int E = in_sizes[2] / 2;

    float *p_h1, *p_q1, *p_agg1, *p_h2, *p_q2, *p_M1, *p_M2, *p_agg2;
    cudaGetSymbolAddress((void**)&p_h1,   g_h1);
    cudaGetSymbolAddress((void**)&p_q1,   g_q1);
    cudaGetSymbolAddress((void**)&p_agg1, g_agg1);
    cudaGetSymbolAddress((void**)&p_h2,   g_h2);
    cudaGetSymbolAddress((void**)&p_q2,   g_q2);
    cudaGetSymbolAddress((void**)&p_M1,   g_M1);
    cudaGetSymbolAddress((void**)&p_M2,   g_M2);
    cudaGetSymbolAddress((void**)&p_agg2, g_agg2);

    dim3 blk(256);

    pack_m1<<<(H1 * B1W + 255) / 256, blk>>>(We1, be1, root1);
    pack_m2<<<(H2 * B2W + 255) / 256, blk>>>(We2, be2, root2);

    // h1 = relu(x @ W1 + b1)            [N,64]@[64,128]  (K=64 %16 ok)
    {
        dim3 g((H1 + GN - 1) / GN, (N + GM - 1) / GM);
        tgemm<<<g, blk>>>(x, W1, p_h1, p_h1, N, H1, D_IN, H1, b1, nullptr, 1);
    }
    // fused q1|agg1 = h1 @ [M1|root1]   [N,128]@[128,1152]; split at 1088
    {
        dim3 g((B1W + GN - 1) / GN, (N + GM - 1) / GM);
        tgemm<<<g, blk>>>(p_h1, p_M1, p_q1, p_agg1, N, B1W, H1, Q1W, nullptr, bias1, 0);
    }
    edge_l1<<<(E + 3) / 4, 128>>>(ea, ei, E);
    relu_copy<<<(N * H2 + 255) / 256, blk>>>(N * H2);
    // fused q2|agg2 = h2 @ [M2|root2]   [N,64]@[64,180]; split at 170
    {
        dim3 g((B2W + GN - 1) / GN, (N + GM - 1) / GM);
        tgemm<<<g, blk>>>(p_h2, p_M2, p_q2, p_agg2, N, B2W, H2, Q2W, nullptr, bias2, 0);
    }
    edge_l2<<<(E + 3) / 4, 128>>>(ea, ei, E);
    log_softmax_rows<<<(N + 255) / 256, blk>>>(out, N);
}